// round 3
// baseline (speedup 1.0000x reference)
#include <cuda_runtime.h>
#include <cuda_bf16.h>
#include <cstdint>

// Problem constants
#define BATCH 8
#define SEQ   2048
#define EMB   126
#define NH    6
#define HD    21
#define PD    24      // padded head dim
#define PD2   12      // u64 pairs per row
#define QTILE 256     // queries per CTA (2 per thread, 128 threads)
#define BK    32      // key tile
#define ROWS  (BATCH*SEQ)   // 16384

// Scratch (device globals; zero-initialized at module load, pads also
// explicitly rewritten to 0 every launch by qkv_gemm_kernel)
__device__ float g_q[BATCH*NH*SEQ*PD];
__device__ float g_k[BATCH*NH*SEQ*PD];
__device__ float g_v[BATCH*NH*SEQ*PD];
__device__ float g_att[ROWS*EMB];

typedef unsigned long long u64;

__device__ __forceinline__ u64 fma2(u64 a, u64 b, u64 c) {
    u64 d; asm("fma.rn.f32x2 %0, %1, %2, %3;" : "=l"(d) : "l"(a), "l"(b), "l"(c)); return d;
}
__device__ __forceinline__ u64 pack2(float lo, float hi) {
    u64 d; asm("mov.b64 %0, {%1, %2};" : "=l"(d) : "f"(lo), "f"(hi)); return d;
}
__device__ __forceinline__ float2 unpack2(u64 v) {
    float2 r; asm("mov.b64 {%0, %1}, %2;" : "=f"(r.x), "=f"(r.y) : "l"(v)); return r;
}

// ---------------------------------------------------------------------------
// Kernel 1: QKV projection. C[16384,378] = X[16384,126] @ Wattn[126,378],
// scattered into g_q/g_k/g_v with padded [B,H,T,PD] layout (pads zeroed).
// ---------------------------------------------------------------------------
__global__ __launch_bounds__(256) void qkv_gemm_kernel(const float* __restrict__ X,
                                                       const float* __restrict__ W) {
    __shared__ float As[64][43];
    __shared__ float Ws[42][65];
    const int bx = blockIdx.x;          // col tile (0..5), 64 cols each
    const int by = blockIdx.y;          // row tile (0..255)
    const int tid = threadIdx.x;
    const int tx = tid & 15, ty = tid >> 4;
    const int row0 = by * 64, col0 = bx * 64;

    float acc[4][4];
#pragma unroll
    for (int i = 0; i < 4; i++)
#pragma unroll
        for (int j = 0; j < 4; j++) acc[i][j] = 0.f;

    for (int k0 = 0; k0 < 126; k0 += 42) {
        for (int idx = tid; idx < 64 * 42; idx += 256) {
            int r = idx / 42, c = idx % 42;
            As[r][c] = X[(size_t)(row0 + r) * 126 + (k0 + c)];
        }
        for (int idx = tid; idx < 42 * 64; idx += 256) {
            int r = idx >> 6, c = idx & 63;
            int gc = col0 + c;
            Ws[r][c] = (gc < 378) ? W[(size_t)(k0 + r) * 378 + gc] : 0.f;
        }
        __syncthreads();
#pragma unroll
        for (int kk = 0; kk < 42; kk++) {
            float a[4], b[4];
#pragma unroll
            for (int i = 0; i < 4; i++) a[i] = As[ty * 4 + i][kk];
#pragma unroll
            for (int j = 0; j < 4; j++) b[j] = Ws[kk][tx * 4 + j];
#pragma unroll
            for (int i = 0; i < 4; i++)
#pragma unroll
                for (int j = 0; j < 4; j++) acc[i][j] = fmaf(a[i], b[j], acc[i][j]);
        }
        __syncthreads();
    }
    // Scatter into q/k/v [B,H,T,PD], zero the pad lanes
#pragma unroll
    for (int i = 0; i < 4; i++) {
        int r = row0 + ty * 4 + i;          // r = b*SEQ + t
        int b_ = r >> 11, t_ = r & 2047;
#pragma unroll
        for (int j = 0; j < 4; j++) {
            int c = col0 + tx * 4 + j;
            if (c >= 378) continue;
            int which = c / 126, cc = c % 126;
            int h = cc / HD, d = cc % HD;
            float* dst = (which == 0) ? g_q : ((which == 1) ? g_k : g_v);
            size_t rowbase = (((size_t)(b_ * NH + h)) * SEQ + t_) * PD;
            dst[rowbase + d] = acc[i][j];
            if (d < PD - HD) dst[rowbase + HD + d] = 0.f;   // pad lanes 21..23
        }
    }
}

// ---------------------------------------------------------------------------
// Kernel 2: Causal flash attention, fp32 f32x2, no-max online softmax,
// 2 queries per thread. Grid: (SEQ/QTILE, NH, BATCH); 128 threads.
// Output to g_att as [B,T,C] (c = h*HD + d) for the proj GEMM.
// ---------------------------------------------------------------------------
__global__ __launch_bounds__(128) void attn_kernel() {
    const int blkq = (gridDim.x - 1) - blockIdx.x;   // heavy blocks first
    const int h = blockIdx.y;
    const int b = blockIdx.z;
    const int tid = threadIdx.x;
    const int base = blkq * QTILE;
    const int qi0 = base + 2 * tid;
    const int qi1 = qi0 + 1;

    __shared__ __align__(16) u64 Ks[BK * PD2];
    __shared__ __align__(16) u64 Vs[BK * PD2];

    const size_t hb = ((size_t)(b * NH + h)) * SEQ * PD;
    const float4* qp0 = (const float4*)(g_q + hb + (size_t)qi0 * PD);
    const float4* qp1 = (const float4*)(g_q + hb + (size_t)qi1 * PD);

    u64 qa[PD2], qb[PD2], acc0[PD2], acc1[PD2];
#pragma unroll
    for (int i = 0; i < 6; i++) {
        float4 v0 = qp0[i]; float4 v1 = qp1[i];
        qa[2 * i]     = pack2(v0.x, v0.y);
        qa[2 * i + 1] = pack2(v0.z, v0.w);
        qb[2 * i]     = pack2(v1.x, v1.y);
        qb[2 * i + 1] = pack2(v1.z, v1.w);
    }
#pragma unroll
    for (int i = 0; i < PD2; i++) { acc0[i] = 0ull; acc1[i] = 0ull; }
    float l0 = 0.f, l1 = 0.f;
    const float scale = 0.21821789f;     // 1/sqrt(21)

    const float4* ksrc = (const float4*)(g_k + hb);
    const float4* vsrc = (const float4*)(g_v + hb);

    const int ntiles = (base + QTILE) / BK;
    for (int kt = 0; kt < ntiles; kt++) {
        const int kstart = kt * BK;
        __syncthreads();
        {   // flat contiguous tile copy: BK*PD floats = 192 float4 per array
            const int fbase = kstart * (PD / 4);
            float4* kd = (float4*)Ks;
            float4* vd = (float4*)Vs;
            kd[tid] = ksrc[fbase + tid];
            vd[tid] = vsrc[fbase + tid];
            if (tid < 64) {
                kd[tid + 128] = ksrc[fbase + tid + 128];
                vd[tid + 128] = vsrc[fbase + tid + 128];
            }
        }
        __syncthreads();
        if (kstart > qi1) continue;       // fully masked for both queries

        if (kstart + BK - 1 <= qi0) {
            // ---- fast path: no causal mask needed ----
#pragma unroll 4
            for (int j = 0; j < BK; j++) {
                const ulonglong2* kr = (const ulonglong2*)&Ks[j * PD2];
                u64 dA = 0ull, dB = 0ull, dC = 0ull, dD = 0ull;
#pragma unroll
                for (int i = 0; i < 3; i++) {
                    ulonglong2 k0 = kr[2 * i], k1 = kr[2 * i + 1];
                    dA = fma2(qa[4 * i],     k0.x, dA);
                    dA = fma2(qa[4 * i + 1], k0.y, dA);
                    dC = fma2(qa[4 * i + 2], k1.x, dC);
                    dC = fma2(qa[4 * i + 3], k1.y, dC);
                    dB = fma2(qb[4 * i],     k0.x, dB);
                    dB = fma2(qb[4 * i + 1], k0.y, dB);
                    dD = fma2(qb[4 * i + 2], k1.x, dD);
                    dD = fma2(qb[4 * i + 3], k1.y, dD);
                }
                float2 e0 = unpack2(dA), e2 = unpack2(dC);
                float2 e1 = unpack2(dB), e3 = unpack2(dD);
                float p0 = __expf((e0.x + e0.y + e2.x + e2.y) * scale);
                float p1 = __expf((e1.x + e1.y + e3.x + e3.y) * scale);
                l0 += p0; l1 += p1;
                u64 p02 = pack2(p0, p0), p12 = pack2(p1, p1);
                const ulonglong2* vr = (const ulonglong2*)&Vs[j * PD2];
#pragma unroll
                for (int i = 0; i < 6; i++) {
                    ulonglong2 vv = vr[i];
                    acc0[2 * i]     = fma2(p02, vv.x, acc0[2 * i]);
                    acc0[2 * i + 1] = fma2(p02, vv.y, acc0[2 * i + 1]);
                    acc1[2 * i]     = fma2(p12, vv.x, acc1[2 * i]);
                    acc1[2 * i + 1] = fma2(p12, vv.y, acc1[2 * i + 1]);
                }
            }
        } else {
            // ---- diagonal tile: per-key causal select ----
            for (int j = 0; j < BK; j++) {
                const ulonglong2* kr = (const ulonglong2*)&Ks[j * PD2];
                u64 dA = 0ull, dB = 0ull, dC = 0ull, dD = 0ull;
#pragma unroll
                for (int i = 0; i < 3; i++) {
                    ulonglong2 k0 = kr[2 * i], k1 = kr[2 * i + 1];
                    dA = fma2(qa[4 * i],     k0.x, dA);
                    dA = fma2(qa[4 * i + 1], k0.y, dA);
                    dC = fma2(qa[4 * i + 2], k1.x, dC);
                    dC = fma2(qa[4 * i + 3], k1.y, dC);
                    dB = fma2(qb[4 * i],     k0.x, dB);
                    dB = fma2(qb[4 * i + 1], k0.y, dB);
                    dD = fma2(qb[4 * i + 2], k1.x, dD);
                    dD = fma2(qb[4 * i + 3], k1.y, dD);
                }
                float2 e0 = unpack2(dA), e2 = unpack2(dC);
                float2 e1 = unpack2(dB), e3 = unpack2(dD);
                const int kj = kstart + j;
                float p0 = (kj <= qi0) ? __expf((e0.x + e0.y + e2.x + e2.y) * scale) : 0.f;
                float p1 = (kj <= qi1) ? __expf((e1.x + e1.y + e3.x + e3.y) * scale) : 0.f;
                l0 += p0; l1 += p1;
                u64 p02 = pack2(p0, p0), p12 = pack2(p1, p1);
                const ulonglong2* vr = (const ulonglong2*)&Vs[j * PD2];
#pragma unroll
                for (int i = 0; i < 6; i++) {
                    ulonglong2 vv = vr[i];
                    acc0[2 * i]     = fma2(p02, vv.x, acc0[2 * i]);
                    acc0[2 * i + 1] = fma2(p02, vv.y, acc0[2 * i + 1]);
                    acc1[2 * i]     = fma2(p12, vv.x, acc1[2 * i]);
                    acc1[2 * i + 1] = fma2(p12, vv.y, acc1[2 * i + 1]);
                }
            }
        }
    }

    const float inv0 = 1.f / l0;
    const float inv1 = 1.f / l1;
    float* op0 = g_att + ((size_t)(b * SEQ + qi0)) * EMB + h * HD;
    float* op1 = g_att + ((size_t)(b * SEQ + qi1)) * EMB + h * HD;
#pragma unroll
    for (int i = 0; i < PD2; i++) {
        float2 v0 = unpack2(acc0[i]);
        float2 v1 = unpack2(acc1[i]);
        int d = 2 * i;
        if (d < HD)     { op0[d]     = v0.x * inv0; op1[d]     = v1.x * inv1; }
        if (d + 1 < HD) { op0[d + 1] = v0.y * inv0; op1[d + 1] = v1.y * inv1; }
    }
}

// ---------------------------------------------------------------------------
// Kernel 3: output projection. Y[16384,126] = g_att[16384,126] @ Wproj[126,126]
// ---------------------------------------------------------------------------
__global__ __launch_bounds__(256) void proj_gemm_kernel(const float* __restrict__ W,
                                                        float* __restrict__ Y) {
    __shared__ float As[64][43];
    __shared__ float Ws[42][65];
    const int bx = blockIdx.x;          // col tile (0..1)
    const int by = blockIdx.y;          // row tile (0..255)
    const int tid = threadIdx.x;
    const int tx = tid & 15, ty = tid >> 4;
    const int row0 = by * 64, col0 = bx * 64;

    float acc[4][4];
#pragma unroll
    for (int i = 0; i < 4; i++)
#pragma unroll
        for (int j = 0; j < 4; j++) acc[i][j] = 0.f;

    for (int k0 = 0; k0 < 126; k0 += 42) {
        for (int idx = tid; idx < 64 * 42; idx += 256) {
            int r = idx / 42, c = idx % 42;
            As[r][c] = g_att[(size_t)(row0 + r) * 126 + (k0 + c)];
        }
        for (int idx = tid; idx < 42 * 64; idx += 256) {
            int r = idx >> 6, c = idx & 63;
            int gc = col0 + c;
            Ws[r][c] = (gc < 126) ? W[(size_t)(k0 + r) * 126 + gc] : 0.f;
        }
        __syncthreads();
#pragma unroll
        for (int kk = 0; kk < 42; kk++) {
            float a[4], b[4];
#pragma unroll
            for (int i = 0; i < 4; i++) a[i] = As[ty * 4 + i][kk];
#pragma unroll
            for (int j = 0; j < 4; j++) b[j] = Ws[kk][tx * 4 + j];
#pragma unroll
            for (int i = 0; i < 4; i++)
#pragma unroll
                for (int j = 0; j < 4; j++) acc[i][j] = fmaf(a[i], b[j], acc[i][j]);
        }
        __syncthreads();
    }
#pragma unroll
    for (int i = 0; i < 4; i++) {
        int r = row0 + ty * 4 + i;
#pragma unroll
        for (int j = 0; j < 4; j++) {
            int c = col0 + tx * 4 + j;
            if (c < 126) Y[(size_t)r * 126 + c] = acc[i][j];
        }
    }
}

// ---------------------------------------------------------------------------
extern "C" void kernel_launch(void* const* d_in, const int* in_sizes, int n_in,
                              void* d_out, int out_size) {
    const float* x      = (const float*)d_in[0];   // [8,2048,126]
    const float* w_attn = (const float*)d_in[1];   // [126,378]
    const float* w_proj = (const float*)d_in[2];   // [126,126]
    float* y = (float*)d_out;                      // [8,2048,126]

    (void)in_sizes; (void)n_in; (void)out_size;

    // 1) QKV projection + padded head scatter
    {
        dim3 grid(6, ROWS / 64);
        qkv_gemm_kernel<<<grid, 256>>>(x, w_attn);
    }
    // 2) Causal attention
    {
        dim3 grid(SEQ / QTILE, NH, BATCH);
        attn_kernel<<<grid, 128>>>();
    }
    // 3) Output projection
    {
        dim3 grid(2, ROWS / 64);
        proj_gemm_kernel<<<grid, 256>>>(w_proj, y);
    }
}

// round 8
// speedup vs baseline: 1.5712x; 1.5712x over previous
#include <cuda_runtime.h>
#include <cuda_bf16.h>
#include <cstdint>

// Problem constants
#define BATCH 8
#define SEQ   2048
#define EMB   126
#define NH    6
#define HD    21
#define PD    24      // padded head dim
#define PD2   12      // u64 pairs per row
#define QTILE 256     // queries per CTA (2 per thread, 128 threads)
#define KCHUNK 256    // keys per CTA (split-K)
#define BK    16      // key tile in smem
#define ROWS  (BATCH*SEQ)   // 16384
#define NCHUNK_TOT 36       // sum_{t=0..7} (t+1)
#define ACCW  24            // accumulator row width (21 acc + l at 21 + pad)

// Scratch (device globals)
__device__ float g_q[BATCH*NH*SEQ*PD];
__device__ float g_k[BATCH*NH*SEQ*PD];
__device__ float g_v[BATCH*NH*SEQ*PD];
__device__ float g_accl[BATCH*NH*SEQ*ACCW];   // per-(b,h,q): 21 acc, [21]=l
__device__ float g_att[ROWS*EMB];

__constant__ int c_tmap[NCHUNK_TOT] = {0, 1,1, 2,2,2, 3,3,3,3, 4,4,4,4,4,
                                       5,5,5,5,5,5, 6,6,6,6,6,6,6, 7,7,7,7,7,7,7,7};
__constant__ int c_cmap[NCHUNK_TOT] = {0, 0,1, 0,1,2, 0,1,2,3, 0,1,2,3,4,
                                       0,1,2,3,4,5, 0,1,2,3,4,5,6, 0,1,2,3,4,5,6,7};

typedef unsigned long long u64;

__device__ __forceinline__ u64 fma2(u64 a, u64 b, u64 c) {
    u64 d; asm("fma.rn.f32x2 %0, %1, %2, %3;" : "=l"(d) : "l"(a), "l"(b), "l"(c)); return d;
}
__device__ __forceinline__ u64 pack2(float lo, float hi) {
    u64 d; asm("mov.b64 %0, {%1, %2};" : "=l"(d) : "f"(lo), "f"(hi)); return d;
}
__device__ __forceinline__ float2 unpack2(u64 v) {
    float2 r; asm("mov.b64 {%0, %1}, %2;" : "=f"(r.x), "=f"(r.y) : "l"(v)); return r;
}

// ---------------------------------------------------------------------------
// Kernel 0: zero the split-K accumulators (graph replays -> must re-zero)
// ---------------------------------------------------------------------------
__global__ __launch_bounds__(256) void zero_accl_kernel() {
    float4* p = (float4*)g_accl;
    const int n = BATCH*NH*SEQ*ACCW/4;    // 589824 float4
    for (int i = blockIdx.x * 256 + threadIdx.x; i < n; i += gridDim.x * 256)
        p[i] = make_float4(0.f, 0.f, 0.f, 0.f);
}

// ---------------------------------------------------------------------------
// Kernel 1: QKV projection -> padded [B,H,T,PD] q/k/v (pads zeroed).
// A tile stored k-major (Ast[kk][row]) so the mma loop uses LDS.128 only.
// ---------------------------------------------------------------------------
__global__ __launch_bounds__(256) void qkv_gemm_kernel(const float* __restrict__ X,
                                                       const float* __restrict__ W) {
    __shared__ __align__(16) float Ast[42][68];   // [k][row], width 68: 16B-aligned rows
    __shared__ __align__(16) float Ws[42][68];    // [k][col]
    const int bx = blockIdx.x;
    const int by = blockIdx.y;
    const int tid = threadIdx.x;
    const int tx = tid & 15, ty = tid >> 4;
    const int row0 = by * 64, col0 = bx * 64;

    float acc[4][4];
#pragma unroll
    for (int i = 0; i < 4; i++)
#pragma unroll
        for (int j = 0; j < 4; j++) acc[i][j] = 0.f;

    for (int k0 = 0; k0 < 126; k0 += 42) {
        for (int idx = tid; idx < 64 * 42; idx += 256) {
            int r = idx / 42, c = idx % 42;
            Ast[c][r] = X[(size_t)(row0 + r) * 126 + (k0 + c)];
        }
        for (int idx = tid; idx < 42 * 64; idx += 256) {
            int r = idx >> 6, c = idx & 63;
            int gc = col0 + c;
            Ws[r][c] = (gc < 378) ? W[(size_t)(k0 + r) * 378 + gc] : 0.f;
        }
        __syncthreads();
#pragma unroll
        for (int kk = 0; kk < 42; kk++) {
            float4 av = *(const float4*)&Ast[kk][ty * 4];
            float4 bv = *(const float4*)&Ws[kk][tx * 4];
            float a[4] = {av.x, av.y, av.z, av.w};
            float b[4] = {bv.x, bv.y, bv.z, bv.w};
#pragma unroll
            for (int i = 0; i < 4; i++)
#pragma unroll
                for (int j = 0; j < 4; j++) acc[i][j] = fmaf(a[i], b[j], acc[i][j]);
        }
        __syncthreads();
    }
#pragma unroll
    for (int i = 0; i < 4; i++) {
        int r = row0 + ty * 4 + i;
        int b_ = r >> 11, t_ = r & 2047;
#pragma unroll
        for (int j = 0; j < 4; j++) {
            int c = col0 + tx * 4 + j;
            if (c >= 378) continue;
            int which = c / 126, cc = c % 126;
            int h = cc / HD, d = cc % HD;
            float* dst = (which == 0) ? g_q : ((which == 1) ? g_k : g_v);
            size_t rowbase = (((size_t)(b_ * NH + h)) * SEQ + t_) * PD;
            dst[rowbase + d] = acc[i][j];
            if (d < PD - HD) dst[rowbase + HD + d] = 0.f;
        }
    }
}

// ---------------------------------------------------------------------------
// Kernel 2: split-K causal attention partial. Each CTA: one (qtile t, kchunk c)
// with c <= t. Uniform 256-key work. No-max softmax; partials combined by
// atomicAdd into g_accl.  (Byte-identical logic to rounds 4-6.)
// ---------------------------------------------------------------------------
template<bool DIAG>
__device__ __forceinline__ void attn_chunk(
    const float4* __restrict__ ksrc, const float4* __restrict__ vsrc, int kbase,
    const u64* qa, const u64* qb, int qi0, int qi1,
    u64* acc0, u64* acc1, float& l0, float& l1,
    u64* Ks, u64* Vs, int tid)
{
    const int NF4 = BK * (PD / 4);    // 96 float4 per tile array
    for (int kt = 0; kt < KCHUNK / BK; kt++) {
        const int kstart = kbase + kt * BK;
        __syncthreads();
        {
            const int fb4 = kstart * (PD / 4);
            float4* kd = (float4*)Ks;
            float4* vd = (float4*)Vs;
            if (tid < NF4) {                 // threads 0..95 copy K
                kd[tid] = ksrc[fb4 + tid];
            } else {                         // threads 96..127 copy first 32 of V
                vd[tid - NF4] = vsrc[fb4 + tid - NF4];
            }
            if (tid < NF4 - 32)              // threads 0..63 copy rest of V
                vd[tid + 32] = vsrc[fb4 + tid + 32];
        }
        __syncthreads();

        float s0[BK], s1[BK];
#pragma unroll
        for (int j = 0; j < BK; j++) {
            const ulonglong2* kr = (const ulonglong2*)&Ks[j * PD2];
            u64 dA = 0ull, dB = 0ull, dC = 0ull, dD = 0ull;
#pragma unroll
            for (int i = 0; i < 3; i++) {
                ulonglong2 k0 = kr[2 * i], k1 = kr[2 * i + 1];
                dA = fma2(qa[4 * i],     k0.x, dA);
                dA = fma2(qa[4 * i + 1], k0.y, dA);
                dC = fma2(qa[4 * i + 2], k1.x, dC);
                dC = fma2(qa[4 * i + 3], k1.y, dC);
                dB = fma2(qb[4 * i],     k0.x, dB);
                dB = fma2(qb[4 * i + 1], k0.y, dB);
                dD = fma2(qb[4 * i + 2], k1.x, dD);
                dD = fma2(qb[4 * i + 3], k1.y, dD);
            }
            float2 e0 = unpack2(dA), e2 = unpack2(dC);
            float2 e1 = unpack2(dB), e3 = unpack2(dD);
            s0[j] = e0.x + e0.y + e2.x + e2.y;   // scale pre-applied to q
            s1[j] = e1.x + e1.y + e3.x + e3.y;
        }
#pragma unroll
        for (int j = 0; j < BK; j++) {
            const int kj = kstart + j;
            float p0, p1;
            if (DIAG) {
                p0 = (kj <= qi0) ? __expf(s0[j]) : 0.f;
                p1 = (kj <= qi1) ? __expf(s1[j]) : 0.f;
            } else {
                p0 = __expf(s0[j]);
                p1 = __expf(s1[j]);
            }
            l0 += p0; l1 += p1;
            u64 p02 = pack2(p0, p0), p12 = pack2(p1, p1);
            const ulonglong2* vr = (const ulonglong2*)&Vs[j * PD2];
#pragma unroll
            for (int i = 0; i < 6; i++) {
                ulonglong2 vv = vr[i];
                acc0[2 * i]     = fma2(p02, vv.x, acc0[2 * i]);
                acc0[2 * i + 1] = fma2(p02, vv.y, acc0[2 * i + 1]);
                acc1[2 * i]     = fma2(p12, vv.x, acc1[2 * i]);
                acc1[2 * i + 1] = fma2(p12, vv.y, acc1[2 * i + 1]);
            }
        }
    }
}

__global__ __launch_bounds__(128) void attn_partial_kernel() {
    const int t = c_tmap[blockIdx.x];
    const int c = c_cmap[blockIdx.x];
    const int h = blockIdx.y;
    const int b = blockIdx.z;
    const int tid = threadIdx.x;
    const int qi0 = t * QTILE + 2 * tid;
    const int qi1 = qi0 + 1;

    __shared__ __align__(16) u64 Ks[BK * PD2];
    __shared__ __align__(16) u64 Vs[BK * PD2];

    const size_t hb = ((size_t)(b * NH + h)) * SEQ * PD;
    const float4* qp0 = (const float4*)(g_q + hb + (size_t)qi0 * PD);
    const float4* qp1 = (const float4*)(g_q + hb + (size_t)qi1 * PD);
    const float scale = 0.21821789f;     // 1/sqrt(21)

    u64 qa[PD2], qb[PD2], acc0[PD2], acc1[PD2];
#pragma unroll
    for (int i = 0; i < 6; i++) {
        float4 v0 = qp0[i]; float4 v1 = qp1[i];
        qa[2 * i]     = pack2(v0.x * scale, v0.y * scale);
        qa[2 * i + 1] = pack2(v0.z * scale, v0.w * scale);
        qb[2 * i]     = pack2(v1.x * scale, v1.y * scale);
        qb[2 * i + 1] = pack2(v1.z * scale, v1.w * scale);
    }
#pragma unroll
    for (int i = 0; i < PD2; i++) { acc0[i] = 0ull; acc1[i] = 0ull; }
    float l0 = 0.f, l1 = 0.f;

    const float4* ksrc = (const float4*)(g_k + hb);
    const float4* vsrc = (const float4*)(g_v + hb);
    const int kbase = c * KCHUNK;

    if (c < t)
        attn_chunk<false>(ksrc, vsrc, kbase, qa, qb, qi0, qi1, acc0, acc1, l0, l1, Ks, Vs, tid);
    else
        attn_chunk<true >(ksrc, vsrc, kbase, qa, qb, qi0, qi1, acc0, acc1, l0, l1, Ks, Vs, tid);

    // Combine partials by addition (no-max softmax is associative)
    float* a0 = g_accl + ((size_t)((b * NH + h) * SEQ) + qi0) * ACCW;
    float* a1 = a0 + ACCW;
#pragma unroll
    for (int i = 0; i < 10; i++) {
        float2 v0 = unpack2(acc0[i]);
        float2 v1 = unpack2(acc1[i]);
        atomicAdd(a0 + 2 * i,     v0.x); atomicAdd(a0 + 2 * i + 1, v0.y);
        atomicAdd(a1 + 2 * i,     v1.x); atomicAdd(a1 + 2 * i + 1, v1.y);
    }
    {   // d = 20
        float2 v0 = unpack2(acc0[10]);
        float2 v1 = unpack2(acc1[10]);
        atomicAdd(a0 + 20, v0.x);
        atomicAdd(a1 + 20, v1.x);
    }
    atomicAdd(a0 + 21, l0);
    atomicAdd(a1 + 21, l1);
}

// ---------------------------------------------------------------------------
// Kernel 3: normalize partials -> g_att [B,T,C] (c = h*HD + d)
// ---------------------------------------------------------------------------
__global__ __launch_bounds__(256) void normalize_kernel() {
    const int gq = blockIdx.x * 256 + threadIdx.x;   // (b*NH+h)*SEQ + q
    if (gq >= BATCH * NH * SEQ) return;
    const int q = gq & (SEQ - 1);
    const int bh = gq >> 11;
    const int h = bh % NH;
    const int b = bh / NH;

    const float4* src = (const float4*)(g_accl + (size_t)gq * ACCW);
    float4 r0 = src[0], r1 = src[1], r2 = src[2], r3 = src[3], r4 = src[4];
    float4 r5 = src[5];
    const float inv = 1.f / r5.y;        // l at index 21
    float* dst = g_att + ((size_t)(b * SEQ + q)) * EMB + h * HD;
    dst[0]  = r0.x * inv; dst[1]  = r0.y * inv; dst[2]  = r0.z * inv; dst[3]  = r0.w * inv;
    dst[4]  = r1.x * inv; dst[5]  = r1.y * inv; dst[6]  = r1.z * inv; dst[7]  = r1.w * inv;
    dst[8]  = r2.x * inv; dst[9]  = r2.y * inv; dst[10] = r2.z * inv; dst[11] = r2.w * inv;
    dst[12] = r3.x * inv; dst[13] = r3.y * inv; dst[14] = r3.z * inv; dst[15] = r3.w * inv;
    dst[16] = r4.x * inv; dst[17] = r4.y * inv; dst[18] = r4.z * inv; dst[19] = r4.w * inv;
    dst[20] = r5.x * inv;
}

// ---------------------------------------------------------------------------
// Kernel 4: output projection. Y[16384,126] = g_att @ Wproj[126,126]
// Same k-major A tile / LDS.128 treatment as kernel 1.
// ---------------------------------------------------------------------------
__global__ __launch_bounds__(256) void proj_gemm_kernel(const float* __restrict__ W,
                                                        float* __restrict__ Y) {
    __shared__ __align__(16) float Ast[42][68];
    __shared__ __align__(16) float Ws[42][68];
    const int bx = blockIdx.x;
    const int by = blockIdx.y;
    const int tid = threadIdx.x;
    const int tx = tid & 15, ty = tid >> 4;
    const int row0 = by * 64, col0 = bx * 64;

    float acc[4][4];
#pragma unroll
    for (int i = 0; i < 4; i++)
#pragma unroll
        for (int j = 0; j < 4; j++) acc[i][j] = 0.f;

    for (int k0 = 0; k0 < 126; k0 += 42) {
        for (int idx = tid; idx < 64 * 42; idx += 256) {
            int r = idx / 42, c = idx % 42;
            Ast[c][r] = g_att[(size_t)(row0 + r) * 126 + (k0 + c)];
        }
        for (int idx = tid; idx < 42 * 64; idx += 256) {
            int r = idx >> 6, c = idx & 63;
            int gc = col0 + c;
            Ws[r][c] = (gc < 126) ? W[(size_t)(k0 + r) * 126 + gc] : 0.f;
        }
        __syncthreads();
#pragma unroll
        for (int kk = 0; kk < 42; kk++) {
            float4 av = *(const float4*)&Ast[kk][ty * 4];
            float4 bv = *(const float4*)&Ws[kk][tx * 4];
            float a[4] = {av.x, av.y, av.z, av.w};
            float b[4] = {bv.x, bv.y, bv.z, bv.w};
#pragma unroll
            for (int i = 0; i < 4; i++)
#pragma unroll
                for (int j = 0; j < 4; j++) acc[i][j] = fmaf(a[i], b[j], acc[i][j]);
        }
        __syncthreads();
    }
#pragma unroll
    for (int i = 0; i < 4; i++) {
        int r = row0 + ty * 4 + i;
#pragma unroll
        for (int j = 0; j < 4; j++) {
            int c = col0 + tx * 4 + j;
            if (c < 126) Y[(size_t)r * 126 + c] = acc[i][j];
        }
    }
}

// ---------------------------------------------------------------------------
extern "C" void kernel_launch(void* const* d_in, const int* in_sizes, int n_in,
                              void* d_out, int out_size) {
    const float* x      = (const float*)d_in[0];   // [8,2048,126]
    const float* w_attn = (const float*)d_in[1];   // [126,378]
    const float* w_proj = (const float*)d_in[2];   // [126,126]
    float* y = (float*)d_out;                      // [8,2048,126]

    (void)in_sizes; (void)n_in; (void)out_size;

    zero_accl_kernel<<<576, 256>>>();
    {
        dim3 grid(6, ROWS / 64);
        qkv_gemm_kernel<<<grid, 256>>>(x, w_attn);
    }
    {
        dim3 grid(NCHUNK_TOT, NH, BATCH);   // 36 x 6 x 8 = 1728 uniform CTAs
        attn_partial_kernel<<<grid, 128>>>();
    }
    normalize_kernel<<<(BATCH * NH * SEQ + 255) / 256, 256>>>();
    {
        dim3 grid(2, ROWS / 64);
        proj_gemm_kernel<<<grid, 256>>>(w_proj, y);
    }
}